// round 17
// baseline (speedup 1.0000x reference)
#include <cuda_runtime.h>
#include <cuda_fp16.h>
#include <cstdint>
#include <cmath>

#define B_ 128
#define T_ 512
#define I_ 256
#define H_ 512
#define RCTAS 128
#define GRPSZ 32          // CTAs per barrier group (one per b-slice)

// ---- static device scratch ----
__device__ float    g_xproj[(size_t)4 * T_ * B_ * H_];  // [g][t][b][h]
__device__ __half   g_xh[(size_t)B_ * T_ * I_];         // x as f16, [bt][k]
__device__ __half   g_whl[(size_t)4 * H_ * 2 * I_];     // W hi/lo interleaved rows
__device__ __half   g_hH[2][B_][H_];                    // h fp16 [buf][b][h]
__device__ unsigned g_cnt[4][32];                       // per-group monotone barrier counter

__device__ __forceinline__ float rcpa(float x) {
    float r;
    asm("rcp.approx.f32 %0, %1;" : "=f"(r) : "f"(x));
    return r;
}
// rational tanh p/q (Eigen coefficients, float-accurate)
__device__ __forceinline__ void tanh_pq(float x, float& p, float& q) {
    x = fminf(fmaxf(x, -7.90531110763549805f), 7.90531110763549805f);
    float x2 = x * x;
    float pp = fmaf(x2, -2.76076847742355e-16f, 2.00018790482477e-13f);
    pp = fmaf(pp, x2, -8.60467152213735e-11f);
    pp = fmaf(pp, x2, 5.12229709037114e-08f);
    pp = fmaf(pp, x2, 1.48572235717979e-05f);
    pp = fmaf(pp, x2, 6.37261928875436e-04f);
    pp = fmaf(pp, x2, 4.89352455891786e-03f);
    p = pp * x;
    float qq = fmaf(x2, 1.19825839466702e-06f, 1.18534705686654e-04f);
    qq = fmaf(qq, x2, 2.26843463243900e-03f);
    q = fmaf(qq, x2, 4.89352518554385e-03f);
}
__device__ __forceinline__ void div4(const float* p, const float* q, float* o) {
    float q01 = q[0] * q[1], q23 = q[2] * q[3];
    float r   = rcpa(q01 * q23);
    float r01 = q23 * r, r23 = q01 * r;
    o[0] = p[0] * (q[1] * r01);
    o[1] = p[1] * (q[0] * r01);
    o[2] = p[2] * (q[3] * r23);
    o[3] = p[3] * (q[2] * r23);
}

// ---- warp MMA helpers ----
__device__ __forceinline__ void ldsm4(uint32_t& r0, uint32_t& r1, uint32_t& r2,
                                      uint32_t& r3, uint32_t addr) {
    asm volatile("ldmatrix.sync.aligned.m8n8.x4.shared.b16 {%0,%1,%2,%3}, [%4];"
                 : "=r"(r0), "=r"(r1), "=r"(r2), "=r"(r3) : "r"(addr));
}
__device__ __forceinline__ void ldsm2(uint32_t& r0, uint32_t& r1, uint32_t addr) {
    asm volatile("ldmatrix.sync.aligned.m8n8.x2.shared.b16 {%0,%1}, [%2];"
                 : "=r"(r0), "=r"(r1) : "r"(addr));
}
__device__ __forceinline__ void mma16816(float* c, uint32_t a0, uint32_t a1,
                                         uint32_t a2, uint32_t a3,
                                         uint32_t b0, uint32_t b1) {
    asm volatile(
        "mma.sync.aligned.m16n8k16.row.col.f32.f16.f16.f32 "
        "{%0,%1,%2,%3}, {%4,%5,%6,%7}, {%8,%9}, {%0,%1,%2,%3};"
        : "+f"(c[0]), "+f"(c[1]), "+f"(c[2]), "+f"(c[3])
        : "r"(a0), "r"(a1), "r"(a2), "r"(a3), "r"(b0), "r"(b1));
}
__device__ __forceinline__ void cpa16(uint32_t sdst, const void* gsrc) {
    asm volatile("cp.async.cg.shared.global [%0], [%1], 16;"
                 :: "r"(sdst), "l"(gsrc) : "memory");
}

// ---------------------------------------------------------------------------
__global__ void lstm_reset() {
    if (threadIdx.x < 4) g_cnt[threadIdx.x][0] = 0;
}

// ---------------------------------------------------------------------------
// prep: x -> f16 ; W -> hi/lo f16 interleaved rows [gh*2 + islo][k]
// ---------------------------------------------------------------------------
__global__ __launch_bounds__(256) void prep_x(const float* __restrict__ x) {
    size_t idx = ((size_t)blockIdx.x * 256 + threadIdx.x) * 8;
    float4 v0 = *(const float4*)(x + idx);
    float4 v1 = *(const float4*)(x + idx + 4);
    __half2 h0 = __floats2half2_rn(v0.x, v0.y);
    __half2 h1 = __floats2half2_rn(v0.z, v0.w);
    __half2 h2 = __floats2half2_rn(v1.x, v1.y);
    __half2 h3 = __floats2half2_rn(v1.z, v1.w);
    uint4 pkt;
    pkt.x = *(uint32_t*)&h0; pkt.y = *(uint32_t*)&h1;
    pkt.z = *(uint32_t*)&h2; pkt.w = *(uint32_t*)&h3;
    *(uint4*)(&g_xh[idx]) = pkt;
}

__global__ __launch_bounds__(64) void prep_w(
    const float* __restrict__ Wz, const float* __restrict__ Ws,
    const float* __restrict__ Wf, const float* __restrict__ Wo)
{
    int gh = blockIdx.x;               // 0..2047
    int g  = gh >> 9;
    const float* W = ((g == 0) ? Wz : (g == 1) ? Ws : (g == 2) ? Wf : Wo);
    const float* src = W + (size_t)(gh & 511) * I_;
    __half* dhi = &g_whl[(size_t)(gh * 2 + 0) * I_];
    __half* dlo = &g_whl[(size_t)(gh * 2 + 1) * I_];
    for (int k = threadIdx.x * 4; k < I_; k += 64 * 4) {
        float4 v = *(const float4*)(src + k);
        __half h0 = __float2half(v.x), h1 = __float2half(v.y);
        __half h2 = __float2half(v.z), h3 = __float2half(v.w);
        __half l0 = __float2half(v.x - __half2float(h0));
        __half l1 = __float2half(v.y - __half2float(h1));
        __half l2 = __float2half(v.z - __half2float(h2));
        __half l3 = __float2half(v.w - __half2float(h3));
        dhi[k] = h0; dhi[k+1] = h1; dhi[k+2] = h2; dhi[k+3] = h3;
        dlo[k] = l0; dlo[k+1] = l1; dlo[k+2] = l2; dlo[k+3] = l3;
    }
}

// ---------------------------------------------------------------------------
// HMMA projection (R15 winner, verbatim): C[bt][gh] = x_f16 . (W_hi+W_lo)^T + b
// ---------------------------------------------------------------------------
__global__ __launch_bounds__(128) void lstm_proj_mma(
    const float* __restrict__ bz, const float* __restrict__ bs,
    const float* __restrict__ bf, const float* __restrict__ bo)
{
    extern __shared__ char sm[];
    const uint32_t smem_base = (uint32_t)__cvta_generic_to_shared(sm);
    const uint32_t SM_X = smem_base;            // 128 rows x 512B = 64KB
    const uint32_t SM_W = smem_base + 65536;    // 64 rows x 512B  = 32KB

    const int tid = threadIdx.x;
    const int w   = tid >> 5;
    const int l   = tid & 31;
    const int wm  = w >> 1;
    const int wn  = w & 1;
    const int r0  = blockIdx.x * 128;
    const int nt  = blockIdx.y;

    {
        const __half* xr = &g_xh[(size_t)(r0 + tid) * I_];
        char* dst = sm + tid * 512;
        const int sx = tid & 7;
#pragma unroll 8
        for (int c = 0; c < 32; c++) {
            uint4 v = *(const uint4*)(xr + c * 8);
            *(uint4*)(dst + ((c ^ sx) << 4)) = v;
        }
    }
    {
        const int row = tid & 63;
        const int h2  = tid >> 6;
        const __half* wr = &g_whl[(size_t)(nt * 64 + row) * I_ + h2 * 128];
        char* dst = sm + 65536 + row * 512;
        const int sx = row & 7;
#pragma unroll 8
        for (int i = 0; i < 16; i++) {
            int c = h2 * 16 + i;
            uint4 v = *(const uint4*)(wr + i * 8);
            *(uint4*)(dst + ((c ^ sx) << 4)) = v;
        }
    }
    __syncthreads();

    uint32_t aBase[4], aXor[4];
#pragma unroll
    for (int i = 0; i < 4; i++) {
        uint32_t row = (uint32_t)(wm * 64 + 16 * i + (l & 15));
        aBase[i] = SM_X + row * 512u;
        aXor[i]  = row & 7;
    }
    const uint32_t aKl = (uint32_t)(l >> 4);
    uint32_t bBase[4], bXor[4];
#pragma unroll
    for (int j = 0; j < 4; j++) {
        uint32_t row = (uint32_t)(wn * 32 + 8 * j + (l & 7));
        bBase[j] = SM_W + row * 512u;
        bXor[j]  = row & 7;
    }
    const uint32_t bKl = (uint32_t)((l >> 3) & 1);

    float acc[4][4][4];
#pragma unroll
    for (int i = 0; i < 4; i++)
#pragma unroll
        for (int j = 0; j < 4; j++)
#pragma unroll
            for (int q = 0; q < 4; q++) acc[i][j][q] = 0.0f;

#pragma unroll 2
    for (int ks = 0; ks < 16; ks++) {
        uint32_t a[4][4];
#pragma unroll
        for (int i = 0; i < 4; i++) {
            uint32_t c = ((uint32_t)(ks * 2) + aKl) ^ aXor[i];
            ldsm4(a[i][0], a[i][1], a[i][2], a[i][3], aBase[i] + (c << 4));
        }
        uint32_t b0[4], b1[4];
#pragma unroll
        for (int j = 0; j < 4; j++) {
            uint32_t c = ((uint32_t)(ks * 2) + bKl) ^ bXor[j];
            ldsm2(b0[j], b1[j], bBase[j] + (c << 4));
        }
#pragma unroll
        for (int i = 0; i < 4; i++)
#pragma unroll
            for (int j = 0; j < 4; j++)
                mma16816(acc[i][j], a[i][0], a[i][1], a[i][2], a[i][3],
                         b0[j], b1[j]);
    }

    const int gh0 = nt * 32;
    const int g   = gh0 >> 9;
    const int hb  = gh0 & 511;
    const float* bias = ((g == 0) ? bz : (g == 1) ? bs : (g == 2) ? bf : bo);
    float bv[4];
    int   hc[4];
#pragma unroll
    for (int j = 0; j < 4; j++) {
        hc[j] = hb + wn * 16 + 4 * j + (l & 3);
        bv[j] = bias[hc[j]];
    }
#pragma unroll
    for (int i = 0; i < 4; i++) {
        int r  = r0 + wm * 64 + 16 * i + (l >> 2);
        int bA = r >> 9,       tA = r & 511;
        int bB = (r + 8) >> 9, tB = (r + 8) & 511;
#pragma unroll
        for (int j = 0; j < 4; j++) {
            float v0 = acc[i][j][0] + acc[i][j][1] + bv[j];
            float v1 = acc[i][j][2] + acc[i][j][3] + bv[j];
            g_xproj[(((size_t)g * T_ + tA) * B_ + bA) * H_ + hc[j]] = v0;
            g_xproj[(((size_t)g * T_ + tB) * B_ + bB) * H_ + hc[j]] = v1;
        }
    }
}

// ---------------------------------------------------------------------------
// persistent HMMA recurrence v4: REDG monotone barrier, split hi/lo acc,
// cp.async B staging. 128 CTAs x 128 thr, warp-local combine (R14/R15 layout).
// ---------------------------------------------------------------------------
__global__ __launch_bounds__(128, 1) void lstm_recur(
    const float* __restrict__ Rz, const float* __restrict__ Rs_,
    const float* __restrict__ Rf, const float* __restrict__ Ro,
    float* __restrict__ out)
{
    extern __shared__ char sm[];
    char* smA = sm;                       // 131072 B (rows 0..127 x 1024B)
    char* smB = sm + 131072;              // 32768 B  (32 n-rows x 1024B)
    const uint32_t smem_base = (uint32_t)__cvta_generic_to_shared(sm);
    const uint32_t SM_A = smem_base;
    const uint32_t SM_B = smem_base + 131072;

    const int tid = threadIdx.x;
    const int w   = tid >> 5;
    const int l   = tid & 31;
    const int hg  = w >> 1;
    const int np  = w & 1;
    const int mt  = blockIdx.x >> 2;
    const int nt  = blockIdx.x & 3;
    const int h0  = mt * 16;
    const int b0  = nt * 32;

    // ---- setup A (R hi/lo f16, gate-paired rows) ----
    {
        const int m  = tid & 63;
        const int kh = (tid >> 6) * 256;
        const int gg = (m >> 3) & 3;
        const int hl = ((m >> 5) << 3) | (m & 7);
        const float* Rp = ((gg == 0) ? Rz : (gg == 1) ? Rs_ : (gg == 2) ? Rf : Ro)
                        + (size_t)(h0 + hl) * H_ + kh;
        char* rowHi = smA + m * 1024;
        char* rowLo = smA + (64 + m) * 1024;
        const int sx = m & 7;
#pragma unroll 8
        for (int k = 0; k < 256; k += 2) {
            float2 v = *(const float2*)(Rp + k);
            __half hv0 = __float2half(v.x);
            __half hv1 = __float2half(v.y);
            float r0 = v.x - __half2float(hv0);
            float r1 = v.y - __half2float(hv1);
            uint32_t hi = (uint32_t)__half_as_ushort(hv0)
                        | ((uint32_t)__half_as_ushort(hv1) << 16);
            uint32_t lo = (uint32_t)__half_as_ushort(__float2half(r0))
                        | ((uint32_t)__half_as_ushort(__float2half(r1)) << 16);
            int byte  = (kh + k) * 2;
            int chunk = byte >> 4;
            int off   = ((chunk ^ sx) << 4) + (byte & 15);
            *(uint32_t*)(rowHi + off) = hi;
            *(uint32_t*)(rowLo + off) = lo;
        }
    }
    __syncthreads();

    const uint32_t aB0  = SM_A + (uint32_t)(hg * 32 + (l & 15)) * 1024u;
    const uint32_t aB1  = aB0 + 16 * 1024u;
    const uint32_t aL0  = aB0 + 64 * 1024u;
    const uint32_t aL1  = aB1 + 64 * 1024u;
    const uint32_t aXor = (uint32_t)(l & 7);
    const uint32_t aKl  = (uint32_t)(l >> 4);
    const uint32_t bXr  = (uint32_t)(l & 7);
    const uint32_t bKl  = (uint32_t)((l >> 3) & 1);
    const uint32_t bBase = SM_B + (uint32_t)(np * 16 + (l & 7)) * 1024u;

    const int hl  = hg * 8 + (l >> 2);
    const int hgl = h0 + hl;
    int nn[4];
    nn[0] = np * 16 + (l & 3) * 2;
    nn[1] = nn[0] + 1;
    nn[2] = nn[0] + 8;
    nn[3] = nn[0] + 9;

    float creg[4] = {0, 0, 0, 0}, hsum[4] = {0, 0, 0, 0};

    const int srow = tid >> 2;
    const int sc0  = (tid & 3) * 16;
    const int sx2  = srow & 7;

    float xz[4], xs[4], xf[4], xo[4];
    {
#pragma unroll
        for (int i = 0; i < 4; i++) {
            size_t off = (size_t)(b0 + nn[i]) * H_ + hgl;
            xz[i] = g_xproj[((size_t)0 * T_ + 0) * B_ * H_ + off];
            xs[i] = g_xproj[((size_t)1 * T_ + 0) * B_ * H_ + off];
            xf[i] = g_xproj[((size_t)2 * T_ + 0) * B_ * H_ + off];
            xo[i] = g_xproj[((size_t)3 * T_ + 0) * B_ * H_ + off];
        }
    }

    for (int t = 0; t < T_; t++) {
        // split hi/lo accumulators: 8 independent mma chains
        float a00h[4] = {0,0,0,0}, a01h[4] = {0,0,0,0};
        float a10h[4] = {0,0,0,0}, a11h[4] = {0,0,0,0};
        float a00l[4] = {0,0,0,0}, a01l[4] = {0,0,0,0};
        float a10l[4] = {0,0,0,0}, a11l[4] = {0,0,0,0};

        if (t > 0) {
            // ---- stage B via cp.async (no register round trip) ----
            {
                const char* gsrc = (const char*)&g_hH[t & 1][b0 + srow][0];
                uint32_t sdst = SM_B + (uint32_t)(srow * 1024);
#pragma unroll
                for (int i = 0; i < 16; i++) {
                    int c = sc0 + i;
                    cpa16(sdst + (uint32_t)((c ^ sx2) << 4), gsrc + c * 16);
                }
                asm volatile("cp.async.commit_group;");
                asm volatile("cp.async.wait_group 0;");
            }
            __syncthreads();

#pragma unroll 4
            for (int ks = 0; ks < 32; ks++) {
                uint32_t aOff = ((((uint32_t)(ks * 2) + aKl) ^ aXor) << 4);
                uint32_t h00, h01, h02, h03, h10, h11, h12, h13;
                uint32_t l00, l01, l02, l03, l10, l11, l12, l13;
                ldsm4(h00, h01, h02, h03, aB0 + aOff);
                ldsm4(h10, h11, h12, h13, aB1 + aOff);
                ldsm4(l00, l01, l02, l03, aL0 + aOff);
                ldsm4(l10, l11, l12, l13, aL1 + aOff);
                uint32_t bOff = ((((uint32_t)(ks * 2) + bKl) ^ bXr) << 4);
                uint32_t b00, b01, b10, b11;
                ldsm2(b00, b01, bBase + bOff);
                ldsm2(b10, b11, bBase + 8192u + bOff);
                mma16816(a00h, h00, h01, h02, h03, b00, b01);
                mma16816(a01h, h00, h01, h02, h03, b10, b11);
                mma16816(a10h, h10, h11, h12, h13, b00, b01);
                mma16816(a11h, h10, h11, h12, h13, b10, b11);
                mma16816(a00l, l00, l01, l02, l03, b00, b01);
                mma16816(a01l, l00, l01, l02, l03, b10, b11);
                mma16816(a10l, l10, l11, l12, l13, b00, b01);
                mma16816(a11l, l10, l11, l12, l13, b10, b11);
            }
        }

        // ---- warp-local combine ----
        {
            float pz[4] = {a00h[0]+a00l[0]+xz[0], a00h[1]+a00l[1]+xz[1],
                           a01h[0]+a01l[0]+xz[2], a01h[1]+a01l[1]+xz[3]};
            float ps[4] = {a00h[2]+a00l[2]+xs[0], a00h[3]+a00l[3]+xs[1],
                           a01h[2]+a01l[2]+xs[2], a01h[3]+a01l[3]+xs[3]};
            float pf[4] = {a10h[0]+a10l[0]+xf[0], a10h[1]+a10l[1]+xf[1],
                           a11h[0]+a11l[0]+xf[2], a11h[1]+a11l[1]+xf[3]};
            float po[4] = {a10h[2]+a10l[2]+xo[0], a10h[3]+a10l[3]+xo[1],
                           a11h[2]+a11l[2]+xo[2], a11h[3]+a11l[3]+xo[3]};

            float pn[4], qn[4];
            float zv[4], sv[4], fv[4], ov[4];
#pragma unroll
            for (int i = 0; i < 4; i++) tanh_pq(pz[i], pn[i], qn[i]);
            div4(pn, qn, zv);
#pragma unroll
            for (int i = 0; i < 4; i++) tanh_pq(ps[i] * 0.5f, pn[i], qn[i]);
            div4(pn, qn, sv);
#pragma unroll
            for (int i = 0; i < 4; i++) sv[i] = fmaf(sv[i], 0.5f, 0.5f);
#pragma unroll
            for (int i = 0; i < 4; i++) tanh_pq(pf[i] * 0.5f, pn[i], qn[i]);
            div4(pn, qn, fv);
#pragma unroll
            for (int i = 0; i < 4; i++) fv[i] = fmaf(fv[i], 0.5f, 0.5f);
#pragma unroll
            for (int i = 0; i < 4; i++) tanh_pq(po[i] * 0.5f, pn[i], qn[i]);
            div4(pn, qn, ov);
#pragma unroll
            for (int i = 0; i < 4; i++) ov[i] = fmaf(ov[i], 0.5f, 0.5f);

            float tc[4];
#pragma unroll
            for (int i = 0; i < 4; i++) {
                float c = fmaf(sv[i], zv[i], fv[i] * creg[i]);
                creg[i] = c;
                tanh_pq(c, pn[i], qn[i]);
            }
            div4(pn, qn, tc);

            if (t < T_ - 1) {
                ushort* hbuf = (ushort*)&g_hH[(t + 1) & 1][0][0];
#pragma unroll
                for (int i = 0; i < 4; i++) {
                    float hn = ov[i] * tc[i];
                    hsum[i] += hn;
                    hbuf[(size_t)(b0 + nn[i]) * H_ + hgl] =
                        __half_as_ushort(__float2half(hn));
                }
            } else {
#pragma unroll
                for (int i = 0; i < 4; i++)
                    out[(size_t)(b0 + nn[i]) * H_ + hgl] =
                        (hsum[i] + ov[i] * tc[i]) * (1.0f / (float)T_);
            }
        }

        if (t < T_ - 1) {
            // prefetch next step's xproj BEFORE the barrier (latency hidden)
            {
#pragma unroll
                for (int i = 0; i < 4; i++) {
                    size_t off = (size_t)(b0 + nn[i]) * H_ + hgl;
                    size_t tb  = (size_t)(t + 1) * B_ * H_;
                    xz[i] = g_xproj[((size_t)0 * T_) * B_ * H_ + tb + off];
                    xs[i] = g_xproj[((size_t)1 * T_) * B_ * H_ + tb + off];
                    xf[i] = g_xproj[((size_t)2 * T_) * B_ * H_ + tb + off];
                    xo[i] = g_xproj[((size_t)3 * T_) * B_ * H_ + tb + off];
                }
            }
            __syncthreads();               // all h stores issued CTA-wide
            if (tid == 0) {
                __threadfence();
                // fire-and-forget arrival (monotone counter, reset per replay)
                asm volatile("red.release.gpu.global.add.u32 [%0], 1;"
                             :: "l"(&g_cnt[nt][0]) : "memory");
                unsigned target = (unsigned)(GRPSZ * (t + 1));
                unsigned v;
                do {
                    asm volatile("ld.acquire.gpu.u32 %0, [%1];"
                                 : "=r"(v) : "l"(&g_cnt[nt][0]) : "memory");
                } while (v < target);
            }
            __syncthreads();
        }
    }
}

// ---------------------------------------------------------------------------
extern "C" void kernel_launch(void* const* d_in, const int* in_sizes, int n_in,
                              void* d_out, int out_size) {
    const float* x  = (const float*)d_in[0];
    const float* Wz = (const float*)d_in[1];
    const float* Ws = (const float*)d_in[2];
    const float* Wf = (const float*)d_in[3];
    const float* Wo = (const float*)d_in[4];
    const float* Rz = (const float*)d_in[5];
    const float* Rs = (const float*)d_in[6];
    const float* Rf = (const float*)d_in[7];
    const float* Ro = (const float*)d_in[8];
    const float* bz = (const float*)d_in[9];
    const float* bs = (const float*)d_in[10];
    const float* bf = (const float*)d_in[11];
    const float* bo = (const float*)d_in[12];

    const int proj_smem  = 65536 + 32768;          // 96KB
    const int recur_smem = 131072 + 32768 + 64;    // ~160KB
    cudaFuncSetAttribute(lstm_proj_mma,
                         cudaFuncAttributeMaxDynamicSharedMemorySize, proj_smem);
    cudaFuncSetAttribute(lstm_recur,
                         cudaFuncAttributeMaxDynamicSharedMemorySize, recur_smem);

    lstm_reset<<<1, 32>>>();
    prep_x<<<(B_ * T_ * I_) / (256 * 8), 256>>>(x);
    prep_w<<<4 * H_, 64>>>(Wz, Ws, Wf, Wo);
    lstm_proj_mma<<<dim3((B_ * T_) / 128, (4 * H_ * 2) / 64), 128, proj_smem>>>(
        bz, bs, bf, bo);
    lstm_recur<<<RCTAS, 128, recur_smem>>>(Rz, Rs, Rf, Ro, (float*)d_out);
}